// round 1
// baseline (speedup 1.0000x reference)
#include <cuda_runtime.h>

// ---------------------------------------------------------------------------
// YOLOv3 detection post-process on GB300.
// Candidates: 32 batches x 3 anchors x (13^2 + 26^2 + 52^2) = 340,704.
// Pipeline: conf-only pass + histogram -> cutoff -> gather -> sort+decode+NMS.
// ---------------------------------------------------------------------------

#define NTOT   340704
#define N13    16224      // 32*3*13*13
#define N26    64896      // 32*3*26*26
#define OFF26  16224
#define OFF52  81120      // N13+N26
#define CAP    4096
#define NBINS  4096
#define TOPK   512

__device__ float               g_conf[NTOT];
__device__ unsigned int        g_hist[NBINS];
__device__ int                 g_cutoff;
__device__ unsigned int        g_count;
__device__ unsigned long long  g_keys[CAP];

__constant__ float c_anchors[3][3][2] = {
    {{116.f, 90.f}, {156.f, 198.f}, {373.f, 326.f}},   // 13x13, stride 32
    {{ 30.f, 61.f}, { 62.f,  45.f}, { 59.f, 119.f}},   // 26x26, stride 16
    {{ 10.f, 13.f}, { 16.f,  30.f}, { 33.f,  23.f}}};  // 52x52, stride 8
__constant__ float c_stride[3] = {32.f, 16.f, 8.f};

// ---------------------------------------------------------------------------
__global__ void k_init() {
    int t = blockIdx.x * blockDim.x + threadIdx.x;
    if (t < NBINS) g_hist[t] = 0u;
    if (t == 0) { g_count = 0u; g_cutoff = 0; }
}

// Map a memory-order id t (scale, b, a, y*W+x) for coalesced conf reads.
__device__ __forceinline__ void split_t(int t, const float* in13, const float* in26,
                                        const float* in52, const float*& in,
                                        int& HW, int& t2, int& off) {
    if (t < N13)              { in = in13; HW = 169;  t2 = t;          off = 0;     }
    else if (t < OFF52)       { in = in26; HW = 676;  t2 = t - OFF26;  off = OFF26; }
    else                      { in = in52; HW = 2704; t2 = t - OFF52;  off = OFF52; }
}

__global__ void k_conf(const float* __restrict__ in13,
                       const float* __restrict__ in26,
                       const float* __restrict__ in52) {
    int t = blockIdx.x * blockDim.x + threadIdx.x;
    if (t >= NTOT) return;
    const float* in; int HW, t2, off;
    split_t(t, in13, in26, in52, in, HW, t2, off);
    int b = t2 / (3 * HW);
    int r = t2 - b * 3 * HW;
    int a = r / HW;
    int p = r - a * HW;                       // y*W + x  (contiguous -> coalesced)
    float logit = in[(b * 255 + a * 85 + 4) * HW + p];
    float conf  = 1.0f / (1.0f + expf(-logit));
    g_conf[t] = conf;
    if (conf > 0.5f) {
        unsigned bits = __float_as_uint(conf);
        unsigned bin  = (bits - 0x3F000000u) >> 11;   // monotone over (0.5, 1.0]
        if (bin > NBINS - 1) bin = NBINS - 1;
        atomicAdd(&g_hist[bin], 1u);
    }
}

// ---------------------------------------------------------------------------
__global__ void k_cutoff() {
    __shared__ unsigned psum[256];
    __shared__ int s_seg;
    __shared__ unsigned s_cumafter;
    int t = threadIdx.x;
    unsigned loc[16];
    unsigned s = 0;
#pragma unroll
    for (int k = 0; k < 16; k++) { loc[k] = g_hist[t * 16 + k]; s += loc[k]; }
    psum[t] = s;
    __syncthreads();
    if (t == 0) {
        unsigned cum = 0; int seg = -1;
        for (int i = 255; i >= 0; --i) {
            if (cum + psum[i] >= TOPK) { seg = i; break; }
            cum += psum[i];
        }
        s_seg = seg; s_cumafter = cum;
        if (seg < 0) g_cutoff = 0;   // fewer than TOPK above threshold
    }
    __syncthreads();
    if (t == s_seg) {
        unsigned cum = s_cumafter;
        int cb = t * 16;
        for (int k = 15; k >= 0; --k) {
            cum += loc[k];
            if (cum >= TOPK) { cb = t * 16 + k; break; }
        }
        g_cutoff = cb;
    }
}

// ---------------------------------------------------------------------------
__global__ void k_gather() {
    int t = blockIdx.x * blockDim.x + threadIdx.x;
    if (t >= NTOT) return;
    float conf = g_conf[t];
    if (!(conf > 0.5f)) return;
    unsigned bits = __float_as_uint(conf);
    unsigned bin  = (bits - 0x3F000000u) >> 11;
    if (bin > NBINS - 1) bin = NBINS - 1;
    if ((int)bin < g_cutoff) return;
    // reference (jax) candidate index: (b, y, x, a) order within scale
    int HW, t2, off; const float* dummy;
    split_t(t, nullptr, nullptr, nullptr, dummy, HW, t2, off);
    int b = t2 / (3 * HW);
    int r = t2 - b * 3 * HW;
    int a = r / HW;
    int p = r - a * HW;
    unsigned g = (unsigned)(off + (b * HW + p) * 3 + a);
    unsigned pos = atomicAdd(&g_count, 1u);
    if (pos < CAP)
        g_keys[pos] = ((unsigned long long)bits << 32) | (0xFFFFFFFFu - g);
}

// ---------------------------------------------------------------------------
__global__ void __launch_bounds__(512) k_final(const float* __restrict__ in13,
                                               const float* __restrict__ in26,
                                               const float* __restrict__ in52,
                                               float* __restrict__ out) {
    __shared__ unsigned long long sk[CAP];           // 32 KB
    __shared__ float cand[TOPK][7];                  // 14 KB
    __shared__ unsigned char keep[TOPK];
    __shared__ int sM, sn;

    int tid = threadIdx.x;
    if (tid == 0) {
        int M = (int)g_count; if (M > CAP) M = CAP;
        int n = TOPK; while (n < M) n <<= 1;
        sM = M; sn = n;
    }
    __syncthreads();
    int M = sM, n = sn;

    for (int k = tid; k < n; k += blockDim.x)
        sk[k] = (k < M) ? g_keys[k] : 0ull;

    // bitonic sort, descending
    for (int ksz = 2; ksz <= n; ksz <<= 1)
        for (int j = ksz >> 1; j > 0; j >>= 1) {
            __syncthreads();
            for (int i = tid; i < n; i += blockDim.x) {
                int l = i ^ j;
                if (l > i) {
                    unsigned long long A = sk[i], B = sk[l];
                    bool dec = ((i & ksz) == 0);
                    if (dec ? (A < B) : (A > B)) { sk[i] = B; sk[l] = A; }
                }
            }
        }
    __syncthreads();

    // decode rank tid
    {
        int r = tid;
        if (r < M) {
            unsigned long long key = sk[r];
            float conf = __uint_as_float((unsigned)(key >> 32));
            unsigned g = 0xFFFFFFFFu - (unsigned)(key & 0xFFFFFFFFu);
            const float* in; int HW, W, sc;
            if (g < N13)        { in = in13; HW = 169;  W = 13; sc = 0; }
            else if (g < OFF52) { in = in26; HW = 676;  W = 26; sc = 1; g -= OFF26; }
            else                { in = in52; HW = 2704; W = 52; sc = 2; g -= OFF52; }
            int a  = g % 3;
            int p  = g / 3;
            int b  = p / HW;
            int pp = p - b * HW;
            int x  = pp % W;
            int y  = pp / W;
            const float* base = in + (b * 255 + a * 85) * HW + pp;
            float tx = 1.0f / (1.0f + expf(-base[0]));
            float ty = 1.0f / (1.0f + expf(-base[HW]));
            float tw = base[2 * HW];
            float th = base[3 * HW];
            float st = c_stride[sc];
            float cx = ((float)x + tx) * st;
            float cy = ((float)y + ty) * st;
            float w  = c_anchors[sc][a][0] * expf(tw);
            float h  = c_anchors[sc][a][1] * expf(th);
            // first-max argmax over 80 classes
            const float* cl = base + 5 * HW;
            float best = cl[0]; int bi = 0;
#pragma unroll 4
            for (int c = 1; c < 80; c++) {
                float v = cl[c * HW];
                if (v > best) { best = v; bi = c; }
            }
            float w0 = w * 0.5f, h0 = h * 0.5f;
            cand[r][0] = conf;
            cand[r][1] = cx - w0;
            cand[r][2] = cy - h0;
            cand[r][3] = cx + w0;
            cand[r][4] = cy + h0;
            cand[r][5] = (float)bi;
            cand[r][6] = (float)b;
            keep[r] = 1;
        } else {
#pragma unroll
            for (int k = 0; k < 7; k++) cand[r][k] = 0.f;
            keep[r] = 0;
        }
    }
    __syncthreads();

    // greedy NMS, reference-exact order
    float x1 = cand[tid][1], y1 = cand[tid][2];
    float x2 = cand[tid][3], y2 = cand[tid][4];
    float areaJ = fmaxf(x2 - x1, 0.f) * fmaxf(y2 - y1, 0.f);
    for (int i = 0; i < TOPK; i++) {
        __syncthreads();
        if (!keep[i]) continue;            // uniform branch (shared value)
        if (tid > i && keep[tid]) {
            float ix1 = cand[i][1], iy1 = cand[i][2];
            float ix2 = cand[i][3], iy2 = cand[i][4];
            float areaI = fmaxf(ix2 - ix1, 0.f) * fmaxf(iy2 - iy1, 0.f);
            float xx1 = fmaxf(x1, ix1), yy1 = fmaxf(y1, iy1);
            float xx2 = fminf(x2, ix2), yy2 = fminf(y2, iy2);
            float inter = fmaxf(xx2 - xx1, 0.f) * fmaxf(yy2 - yy1, 0.f);
            float iou = inter / (areaI + areaJ - inter + 1e-9f);
            if (iou > 0.3f) keep[tid] = 0;
        }
    }
    __syncthreads();

    float kf = keep[tid] ? 1.0f : 0.0f;
#pragma unroll
    for (int k = 0; k < 7; k++)
        out[tid * 7 + k] = cand[tid][k] * kf;
}

// ---------------------------------------------------------------------------
extern "C" void kernel_launch(void* const* d_in, const int* in_sizes, int n_in,
                              void* d_out, int out_size) {
    const float* in13 = (const float*)d_in[0];
    const float* in26 = (const float*)d_in[1];
    const float* in52 = (const float*)d_in[2];
    float* out = (float*)d_out;

    k_init<<<16, 256>>>();
    k_conf<<<(NTOT + 255) / 256, 256>>>(in13, in26, in52);
    k_cutoff<<<1, 256>>>();
    k_gather<<<(NTOT + 255) / 256, 256>>>();
    k_final<<<1, 512>>>(in13, in26, in52, out);
}

// round 2
// speedup vs baseline: 1.3282x; 1.3282x over previous
#include <cuda_runtime.h>

// ---------------------------------------------------------------------------
// YOLOv3 detection post-process, round 2.
// conf pass + histogram -> cutoff -> gather -> 1-block sort ->
// warp-per-candidate decode (full chip) -> bitmask IoU -> ffs greedy NMS.
// ---------------------------------------------------------------------------

#define NTOT   340704
#define N13    16224      // 32*3*13*13
#define OFF26  16224
#define OFF52  81120      // N13 + N26
#define CAP    4096
#define NBINS  4096
#define TOPK   512

__device__ float4              g_conf4[NTOT / 4];
__device__ unsigned int        g_hist[NBINS];
__device__ int                 g_cutoff;
__device__ unsigned int        g_count;
__device__ unsigned long long  g_keys[CAP];
__device__ unsigned long long  g_skeys[TOPK];
__device__ int                 g_Mv;                 // valid ranks = min(count, 512)
__device__ float               g_cand[TOPK * 7];
__device__ unsigned int        g_mask[TOPK * 16];    // iou>thr & j>i bit rows

__constant__ float c_anchors[3][3][2] = {
    {{116.f, 90.f}, {156.f, 198.f}, {373.f, 326.f}},   // 13x13, stride 32
    {{ 30.f, 61.f}, { 62.f,  45.f}, { 59.f, 119.f}},   // 26x26, stride 16
    {{ 10.f, 13.f}, { 16.f,  30.f}, { 33.f,  23.f}}};  // 52x52, stride 8
__constant__ float c_stride[3] = {32.f, 16.f, 8.f};

// ---------------------------------------------------------------------------
__global__ void k_init() {
    int t = blockIdx.x * blockDim.x + threadIdx.x;
    if (t < NBINS) g_hist[t] = 0u;
    if (t == 0) { g_count = 0u; g_cutoff = 0; }
}

// ---------------------------------------------------------------------------
__global__ void __launch_bounds__(256) k_conf(const float* __restrict__ in13,
                                              const float* __restrict__ in26,
                                              const float* __restrict__ in52) {
    int t0 = (blockIdx.x * blockDim.x + threadIdx.x) * 4;
    if (t0 >= NTOT) return;
    float c4[4];
#pragma unroll
    for (int q = 0; q < 4; q++) {
        int t = t0 + q;
        const float* in; int HW, t2;
        if (t < N13)        { in = in13; HW = 169;  t2 = t;         }
        else if (t < OFF52) { in = in26; HW = 676;  t2 = t - OFF26; }
        else                { in = in52; HW = 2704; t2 = t - OFF52; }
        int b = t2 / (3 * HW);
        int r = t2 - b * 3 * HW;
        int a = r / HW;
        int p = r - a * HW;
        float logit = in[(b * 255 + a * 85 + 4) * HW + p];
        float conf  = 1.0f / (1.0f + expf(-logit));
        c4[q] = conf;
        if (conf > 0.5f) {
            unsigned bin = (__float_as_uint(conf) - 0x3F000000u) >> 11;
            if (bin > NBINS - 1) bin = NBINS - 1;
            atomicAdd(&g_hist[bin], 1u);
        }
    }
    g_conf4[t0 >> 2] = make_float4(c4[0], c4[1], c4[2], c4[3]);
}

// ---------------------------------------------------------------------------
__global__ void k_cutoff() {
    __shared__ unsigned psum[256];
    __shared__ int s_seg;
    __shared__ unsigned s_cumafter;
    int t = threadIdx.x;
    unsigned loc[16];
    unsigned s = 0;
#pragma unroll
    for (int k = 0; k < 16; k++) { loc[k] = g_hist[t * 16 + k]; s += loc[k]; }
    psum[t] = s;
    __syncthreads();
    if (t == 0) {
        unsigned cum = 0; int seg = -1;
        for (int i = 255; i >= 0; --i) {
            if (cum + psum[i] >= TOPK) { seg = i; break; }
            cum += psum[i];
        }
        s_seg = seg; s_cumafter = cum;
        if (seg < 0) g_cutoff = 0;   // fewer than TOPK above threshold
    }
    __syncthreads();
    if (t == s_seg) {
        unsigned cum = s_cumafter;
        int cb = t * 16;
        for (int k = 15; k >= 0; --k) {
            cum += loc[k];
            if (cum >= TOPK) { cb = t * 16 + k; break; }
        }
        g_cutoff = cb;
    }
}

// ---------------------------------------------------------------------------
__global__ void __launch_bounds__(256) k_gather() {
    int t0 = (blockIdx.x * blockDim.x + threadIdx.x) * 4;
    if (t0 >= NTOT) return;
    float4 c4 = g_conf4[t0 >> 2];
    float cv[4] = {c4.x, c4.y, c4.z, c4.w};
    int cut = g_cutoff;
#pragma unroll
    for (int q = 0; q < 4; q++) {
        float conf = cv[q];
        if (!(conf > 0.5f)) continue;
        unsigned bits = __float_as_uint(conf);
        unsigned bin  = (bits - 0x3F000000u) >> 11;
        if (bin > NBINS - 1) bin = NBINS - 1;
        if ((int)bin < cut) continue;
        int t = t0 + q;
        int HW, t2, off;
        if (t < N13)        { HW = 169;  t2 = t;         off = 0;     }
        else if (t < OFF52) { HW = 676;  t2 = t - OFF26; off = OFF26; }
        else                { HW = 2704; t2 = t - OFF52; off = OFF52; }
        int b = t2 / (3 * HW);
        int r = t2 - b * 3 * HW;
        int a = r / HW;
        int p = r - a * HW;
        unsigned g = (unsigned)(off + (b * HW + p) * 3 + a);
        unsigned pos = atomicAdd(&g_count, 1u);
        if (pos < CAP)
            g_keys[pos] = ((unsigned long long)bits << 32) | (0xFFFFFFFFu - g);
    }
}

// ---------------------------------------------------------------------------
__global__ void __launch_bounds__(1024) k_sort() {
    __shared__ unsigned long long sk[CAP];      // 32 KB
    __shared__ int sM, sn;
    int tid = threadIdx.x;
    if (tid == 0) {
        int M = (int)g_count; if (M > CAP) M = CAP;
        int n = TOPK; while (n < M) n <<= 1;
        sM = M; sn = n;
        g_Mv = (M < TOPK) ? M : TOPK;
    }
    __syncthreads();
    int M = sM, n = sn;
    for (int k = tid; k < n; k += 1024)
        sk[k] = (k < M) ? g_keys[k] : 0ull;
    for (int ksz = 2; ksz <= n; ksz <<= 1)
        for (int j = ksz >> 1; j > 0; j >>= 1) {
            __syncthreads();
            for (int i = tid; i < n; i += 1024) {
                int l = i ^ j;
                if (l > i) {
                    unsigned long long A = sk[i], B = sk[l];
                    bool dec = ((i & ksz) == 0);
                    if (dec ? (A < B) : (A > B)) { sk[i] = B; sk[l] = A; }
                }
            }
        }
    __syncthreads();
    if (tid < TOPK) g_skeys[tid] = sk[tid];
}

// ---------------------------------------------------------------------------
// One warp per candidate; 64 blocks x 256 threads = 512 warps.
__global__ void __launch_bounds__(256) k_decode(const float* __restrict__ in13,
                                                const float* __restrict__ in26,
                                                const float* __restrict__ in52) {
    int r    = blockIdx.x * (blockDim.x >> 5) + (threadIdx.x >> 5);
    int lane = threadIdx.x & 31;
    if (r >= TOPK) return;
    int M = g_Mv;
    if (r >= M) {
        if (lane < 7) g_cand[r * 7 + lane] = 0.f;
        return;
    }
    unsigned long long key = g_skeys[r];
    float conf = __uint_as_float((unsigned)(key >> 32));
    unsigned g = 0xFFFFFFFFu - (unsigned)(key & 0xFFFFFFFFu);
    const float* in; int HW, W, sc;
    if (g < N13)        { in = in13; HW = 169;  W = 13; sc = 0; }
    else if (g < OFF52) { in = in26; HW = 676;  W = 26; sc = 1; g -= OFF26; }
    else                { in = in52; HW = 2704; W = 52; sc = 2; g -= OFF52; }
    int a  = g % 3;
    int p  = g / 3;
    int b  = p / HW;
    int pp = p - b * HW;
    int x  = pp % W;
    int y  = pp / W;
    const float* base = in + (b * 255 + a * 85) * HW + pp;

    // lanes 0-3 fetch tx,ty,tw,th channels
    float chv = 0.f;
    if (lane < 4) chv = base[lane * HW];

    // 80-class argmax, first-max tie break
    float bv = -3.4e38f; int bi = 127;
#pragma unroll
    for (int k = 0; k < 3; k++) {
        int c = lane + 32 * k;
        if (c < 80) {
            float v = base[(5 + c) * HW];
            if (v > bv) { bv = v; bi = c; }
        }
    }
#pragma unroll
    for (int off = 16; off; off >>= 1) {
        float ov = __shfl_xor_sync(0xFFFFFFFFu, bv, off);
        int   oi = __shfl_xor_sync(0xFFFFFFFFu, bi, off);
        if (ov > bv || (ov == bv && oi < bi)) { bv = ov; bi = oi; }
    }
    float t0 = __shfl_sync(0xFFFFFFFFu, chv, 0);
    float t1 = __shfl_sync(0xFFFFFFFFu, chv, 1);
    float t2 = __shfl_sync(0xFFFFFFFFu, chv, 2);
    float t3 = __shfl_sync(0xFFFFFFFFu, chv, 3);
    if (lane == 0) {
        float tx = 1.0f / (1.0f + expf(-t0));
        float ty = 1.0f / (1.0f + expf(-t1));
        float st = c_stride[sc];
        float cx = ((float)x + tx) * st;
        float cy = ((float)y + ty) * st;
        float w  = c_anchors[sc][a][0] * expf(t2);
        float h  = c_anchors[sc][a][1] * expf(t3);
        float w0 = w * 0.5f, h0 = h * 0.5f;
        float* o = &g_cand[r * 7];
        o[0] = conf;
        o[1] = cx - w0;
        o[2] = cy - h0;
        o[3] = cx + w0;
        o[4] = cy + h0;
        o[5] = (float)bi;
        o[6] = (float)b;
    }
}

// ---------------------------------------------------------------------------
// 64 blocks x 512 threads; block handles 8 rows. Bit (i,j) = iou>thr && j>i.
__global__ void __launch_bounds__(512) k_ioumask() {
    int j = threadIdx.x;
    float jx1 = g_cand[j * 7 + 1], jy1 = g_cand[j * 7 + 2];
    float jx2 = g_cand[j * 7 + 3], jy2 = g_cand[j * 7 + 4];
    float areaJ = fmaxf(jx2 - jx1, 0.f) * fmaxf(jy2 - jy1, 0.f);
    int wid = j >> 5, lane = j & 31;
#pragma unroll
    for (int q = 0; q < 8; q++) {
        int i = blockIdx.x * 8 + q;
        float ix1 = g_cand[i * 7 + 1], iy1 = g_cand[i * 7 + 2];
        float ix2 = g_cand[i * 7 + 3], iy2 = g_cand[i * 7 + 4];
        float areaI = fmaxf(ix2 - ix1, 0.f) * fmaxf(iy2 - iy1, 0.f);
        float xx1 = fmaxf(ix1, jx1), yy1 = fmaxf(iy1, jy1);
        float xx2 = fminf(ix2, jx2), yy2 = fminf(iy2, jy2);
        float inter = fmaxf(xx2 - xx1, 0.f) * fmaxf(yy2 - yy1, 0.f);
        float iou = inter / (areaI + areaJ - inter + 1e-9f);
        unsigned bal = __ballot_sync(0xFFFFFFFFu, (iou > 0.3f) && (j > i));
        if (lane == 0) g_mask[i * 16 + wid] = bal;
    }
}

// ---------------------------------------------------------------------------
__global__ void __launch_bounds__(512) k_nms_out(float* __restrict__ out) {
    __shared__ unsigned smask[TOPK * 16];       // 32 KB
    __shared__ unsigned skeep[16];
    int tid = threadIdx.x;
    for (int idx = tid; idx < TOPK * 16; idx += 512)
        smask[idx] = g_mask[idx];
    if (tid < 16) {
        int M = g_Mv;
        int lo = tid * 32;
        unsigned w;
        if (M >= lo + 32)      w = 0xFFFFFFFFu;
        else if (M <= lo)      w = 0u;
        else                   w = (1u << (M - lo)) - 1u;
        skeep[tid] = w;
    }
    __syncthreads();
    if (tid == 0) {
        unsigned kw[16];
#pragma unroll
        for (int k = 0; k < 16; k++) kw[k] = skeep[k];
        for (int w = 0; w < 16; w++) {
            unsigned bits = kw[w];
            while (bits) {
                int b = __ffs(bits) - 1;
                const unsigned* mrow = &smask[(w * 32 + b) * 16];
                for (int u = w; u < 16; u++) kw[u] &= ~mrow[u];
                bits = kw[w] & (0xFFFFFFFEu << b);   // strictly greater than b
            }
        }
#pragma unroll
        for (int k = 0; k < 16; k++) skeep[k] = kw[k];
    }
    __syncthreads();
    float kf = ((skeep[tid >> 5] >> (tid & 31)) & 1u) ? 1.0f : 0.0f;
#pragma unroll
    for (int k = 0; k < 7; k++)
        out[tid * 7 + k] = g_cand[tid * 7 + k] * kf;
}

// ---------------------------------------------------------------------------
extern "C" void kernel_launch(void* const* d_in, const int* in_sizes, int n_in,
                              void* d_out, int out_size) {
    const float* in13 = (const float*)d_in[0];
    const float* in26 = (const float*)d_in[1];
    const float* in52 = (const float*)d_in[2];
    float* out = (float*)d_out;

    int conf_blocks = (NTOT / 4 + 255) / 256;
    k_init<<<16, 256>>>();
    k_conf<<<conf_blocks, 256>>>(in13, in26, in52);
    k_cutoff<<<1, 256>>>();
    k_gather<<<conf_blocks, 256>>>();
    k_sort<<<1, 1024>>>();
    k_decode<<<64, 256>>>(in13, in26, in52);
    k_ioumask<<<64, 512>>>();
    k_nms_out<<<1, 512>>>(out);
}